// round 15
// baseline (speedup 1.0000x reference)
#include <cuda_runtime.h>
#include <cuda_bf16.h>
#include <math.h>
#include <stdint.h>

#define BATCH   2048
#define IN_DIM  376
#define HID     1024
#define NOUT    17
#define NCELLS  6
#define NOPS    5
#define KP0     384            // IN_DIM padded to multiple of BK

#define BM 128
#define BN 32
#define BK 32
#define NTHREADS 256

// smem (u32 units): per buffer: A 2 planes x 128 rows x 20, B 8 (op,plane) x 32 x 20
#define A_ROW_STRIDE 20
#define A_PLANE      (128 * A_ROW_STRIDE)          // 2560 u32
#define B_TILE       (32 * A_ROW_STRIDE)           // 640 u32
#define BUF_U32      (2 * A_PLANE + 8 * B_TILE)    // 10240 u32 = 40 KB
#define OFF_B_U32    (2 * A_PLANE)
#define BUF_BYTES    (BUF_U32 * 4)
#define SMEM_BYTES   (2 * BUF_U32 * 4)             // 80 KB

// prepass combined-kernel role boundaries (1D grid)
#define PRE_X_BLOCKS  3072                          // BATCH*KP0/256
#define PRE_T0_BLOCKS 3840                          // (KP0/64)*(HID/32)*20
#define PRE_TOTAL     (1 + PRE_X_BLOCKS + PRE_T0_BLOCKS)

// ---------------------------------------------------------------------------
// device scratch
// ---------------------------------------------------------------------------
__device__ float g_acc[5u * BATCH * HID];
__device__ float g_z[150];
// pre-split, transposed weights: [pair][n][k] bf16, k contiguous
__device__ __nv_bfloat16 g_wt0_hi[20u * HID * KP0];
__device__ __nv_bfloat16 g_wt0_lo[20u * HID * KP0];
__device__ __nv_bfloat16 g_wth_hi[40u * HID * HID];
__device__ __nv_bfloat16 g_wth_lo[40u * HID * HID];
// pre-split activations: x planes + node 1..4 planes ([m][k], k contiguous)
__device__ __nv_bfloat16 g_x_hi[(size_t)BATCH * KP0];
__device__ __nv_bfloat16 g_x_lo[(size_t)BATCH * KP0];
__device__ __nv_bfloat16 g_a_hi[4u * BATCH * HID];
__device__ __nv_bfloat16 g_a_lo[4u * BATCH * HID];

// ---------------------------------------------------------------------------
__device__ __forceinline__ void bf16split(float a, __nv_bfloat16& hi, __nv_bfloat16& lo) {
    hi = __float2bfloat16_rn(a);
    lo = __float2bfloat16_rn(a - __bfloat162float(hi));
}
__device__ __forceinline__ uint32_t packbf2(__nv_bfloat16 a, __nv_bfloat16 b) {
    __nv_bfloat162 v(a, b);
    return *reinterpret_cast<uint32_t*>(&v);
}
__device__ __forceinline__ uint32_t smem_u32(const void* p) {
    uint32_t a;
    asm("{ .reg .u64 t; cvta.to.shared.u64 t, %1; cvt.u32.u64 %0, t; }"
        : "=r"(a) : "l"(p));
    return a;
}
__device__ __forceinline__ void ldmx4(uint32_t* r, uint32_t addr) {
    asm volatile("ldmatrix.sync.aligned.m8n8.x4.shared.b16 {%0,%1,%2,%3}, [%4];"
        : "=r"(r[0]), "=r"(r[1]), "=r"(r[2]), "=r"(r[3]) : "r"(addr));
}
__device__ __forceinline__ void cp16(uint32_t dst, const void* src) {
    asm volatile("cp.async.cg.shared.global [%0], [%1], 16;" :: "r"(dst), "l"(src));
}
__device__ __forceinline__ void cp_commit() { asm volatile("cp.async.commit_group;"); }
__device__ __forceinline__ void cp_wait0()  { asm volatile("cp.async.wait_group 0;" ::: "memory"); }

__device__ __forceinline__ void mma16816(float* d, const uint32_t* a,
                                         uint32_t b0, uint32_t b1) {
    asm volatile(
        "mma.sync.aligned.m16n8k16.row.col.f32.bf16.bf16.f32 "
        "{%0,%1,%2,%3}, {%4,%5,%6,%7}, {%8,%9}, {%0,%1,%2,%3};\n"
        : "+f"(d[0]), "+f"(d[1]), "+f"(d[2]), "+f"(d[3])
        : "r"(a[0]), "r"(a[1]), "r"(a[2]), "r"(a[3]), "r"(b0), "r"(b1));
}

// edge-pair -> (source stage s, target i) map for Wh
__device__ __forceinline__ void pair_to_edge(int e, int& s, int& i) {
    if      (e < 4) { s = 1; i = e + 2; }
    else if (e < 7) { s = 2; i = e - 4 + 3; }
    else if (e < 9) { s = 3; i = e - 7 + 4; }
    else            { s = 4; i = 5; }
}

// ---------------------------------------------------------------------------
// Combined prepass (1D grid, 256 threads):
//   b == 0                     : z = softmax(log_alphas + eps)
//   b in [1, 1+PRE_X_BLOCKS)   : split x into bf16 hi/lo planes
//   b in [.., +PRE_T0_BLOCKS)  : transpose + split W0 (64k x 32n tiles)
// ---------------------------------------------------------------------------
__global__ void prepass_kernel(const float* __restrict__ la, const float* __restrict__ eps,
                               const float* __restrict__ x, const float* __restrict__ W0)
{
    __shared__ float ts[64][33];
    const int b = blockIdx.x;
    const int tid = threadIdx.x;

    if (b == 0) {
        if (tid < 30) {
            float v[NOPS], mx = -1e30f;
            #pragma unroll
            for (int o = 0; o < NOPS; o++) { v[o] = la[tid*NOPS+o] + eps[tid*NOPS+o]; mx = fmaxf(mx, v[o]); }
            float s = 0.f;
            #pragma unroll
            for (int o = 0; o < NOPS; o++) { v[o] = expf(v[o] - mx); s += v[o]; }
            float inv = 1.f / s;
            #pragma unroll
            for (int o = 0; o < NOPS; o++) g_z[tid*NOPS+o] = v[o] * inv;
        }
        return;
    }
    if (b < 1 + PRE_X_BLOCKS) {
        const int idx = (b - 1) * 256 + tid;        // [0, BATCH*KP0)
        const int m = idx / KP0, k = idx % KP0;
        float v = (k < IN_DIM) ? x[(size_t)m * IN_DIM + k] : 0.f;
        __nv_bfloat16 hi, lo; bf16split(v, hi, lo);
        g_x_hi[(size_t)m * KP0 + k] = hi;
        g_x_lo[(size_t)m * KP0 + k] = lo;
        return;
    }
    // ---- split_t0 role ----
    {
        const int t = b - (1 + PRE_X_BLOCKS);       // [0, 3840)
        const int pair = t / 192;                   // [0, 20)
        const int rem  = t % 192;
        const int nb = (rem / 6) * 32;
        const int kb = (rem % 6) * 64;
        const int i = (pair >> 2) + 1, op = pair & 3;
        const float* src = W0 + ((size_t)(i * NOPS + op)) * IN_DIM * HID;
        const int tx = tid & 31, ty = tid >> 5;     // (32, 8)
        #pragma unroll
        for (int r = 0; r < 8; r++) {
            int k = ty * 8 + r;                     // 0..63
            ts[k][tx] = (kb + k < IN_DIM) ? src[(size_t)(kb + k) * HID + nb + tx] : 0.f;
        }
        __syncthreads();
        uint32_t* dh = (uint32_t*)(g_wt0_hi + (size_t)pair * HID * KP0);
        uint32_t* dl = (uint32_t*)(g_wt0_lo + (size_t)pair * HID * KP0);
        #pragma unroll
        for (int r = 0; r < 4; r++) {
            const int n = ty * 4 + r;               // 0..31
            __nv_bfloat16 h0, l0, h1, l1;
            bf16split(ts[tx * 2][n], h0, l0);
            bf16split(ts[tx * 2 + 1][n], h1, l1);
            const size_t w = ((size_t)(nb + n) * KP0 + kb) / 2 + tx;
            dh[w] = packbf2(h0, h1);
            dl[w] = packbf2(l0, l1);
        }
    }
}

// ---------------------------------------------------------------------------
// Stage GEMM: bf16x3 mma.sync; A and B both via cp.async (pre-split planes).
// KP compile-time; producers register-thin. CTA = [128 x 32] x 4 ops;
// warp = 32x16; 2 CTAs/SM.
// stage 0: 1D grid of 3072 blocks; every 6th block (bid%6==0) is a
//   split-role block that transposes+splits Wh (needed only from stage 1) —
//   DRAM-bound work hidden under tensor-bound stage-0 compute.
// stages 1-4: grid = (BATCH/BM, HID/BN, 5-stage).
// ---------------------------------------------------------------------------
template<int KP>
__global__ __launch_bounds__(NTHREADS, 2)
void stage_mma_kernel(int stage, const float* __restrict__ b0,
                      const float* __restrict__ bh, const float* __restrict__ Wh)
{
    extern __shared__ uint32_t smem[];
    const uint32_t sbase = smem_u32(smem);
    const int tid = threadIdx.x;

    int bx, by, iz;
    if (stage == 0) {
        const int bid = blockIdx.x;
        if (bid % 6 == 0) {
            // ---- split_th role: transpose + bf16-split Wh, 40 pairs ----
            float (*ts)[33] = reinterpret_cast<float(*)[33]>(smem);
            const int s = bid / 6;                  // [0, 512)
            const int kb = (s >> 5) * 64;
            const int nb = (s & 31) * 32;
            const int tx = tid & 31, ty = tid >> 5;
            #pragma unroll 1
            for (int pair = 0; pair < 40; pair++) {
                int ss, ii; pair_to_edge(pair >> 2, ss, ii);
                const int op = pair & 3;
                const float* src = Wh +
                    ((size_t)(((ss - 1) * NCELLS + ii) * NOPS + op)) * HID * HID;
                #pragma unroll
                for (int r = 0; r < 8; r++) {
                    int k = ty * 8 + r;
                    ts[k][tx] = src[(size_t)(kb + k) * HID + nb + tx];
                }
                __syncthreads();
                uint32_t* dh = (uint32_t*)(g_wth_hi + (size_t)pair * HID * HID);
                uint32_t* dl = (uint32_t*)(g_wth_lo + (size_t)pair * HID * HID);
                #pragma unroll
                for (int r = 0; r < 4; r++) {
                    const int n = ty * 4 + r;
                    __nv_bfloat16 h0, l0, h1, l1;
                    bf16split(ts[tx * 2][n], h0, l0);
                    bf16split(ts[tx * 2 + 1][n], h1, l1);
                    const size_t w = ((size_t)(nb + n) * HID + kb) / 2 + tx;
                    dh[w] = packbf2(h0, h1);
                    dl[w] = packbf2(l0, l1);
                }
                __syncthreads();
            }
            return;
        }
        const int idx = bid - bid / 6 - 1;          // [0, 2560)
        iz = idx >> 9;
        const int rem = idx & 511;
        by = rem >> 4;
        bx = rem & 15;
    } else {
        bx = blockIdx.x; by = blockIdx.y; iz = blockIdx.z;
    }

    const int i   = stage + 1 + iz;
    const int bm0 = bx * BM;
    const int bn0 = by * BN;

    const __nv_bfloat16 *Ahi, *Alo, *Bhi, *Blo;
    const float* bias;
    if (stage == 0) {
        Ahi = g_x_hi; Alo = g_x_lo;
        const size_t pb = (size_t)((i - 1) * 4) * HID * KP;
        Bhi = g_wt0_hi + pb; Blo = g_wt0_lo + pb;
        bias = b0 + (size_t)(i * NOPS) * HID;
    } else {
        Ahi = g_a_hi + (size_t)(stage - 1) * BATCH * HID;
        Alo = g_a_lo + (size_t)(stage - 1) * BATCH * HID;
        static const int eoff[5] = {0, 0, 4, 7, 9};
        const int e = eoff[stage] + (i - stage - 1);
        const size_t pb = (size_t)(e * 4) * HID * KP;
        Bhi = g_wth_hi + pb; Blo = g_wth_lo + pb;
        bias = bh + (size_t)(((stage - 1) * NCELLS + i) * NOPS) * HID;
    }
    float* accOut = g_acc + (size_t)(i - 1) * BATCH * HID;
    const float* zp = g_z + (stage * NCELLS + i) * NOPS;

    const int w    = tid >> 5, lane = tid & 31;
    const int wm   = (w & 3) * 32;          // warp M offset
    const int wn   = (w >> 2) * 16;         // warp N offset
    const int qr   = lane >> 2;             // t/4
    const int qk   = lane & 3;              // t%4
    const int lg   = lane >> 3;             // ldmatrix group 0..3
    const int lr   = lane & 7;              // ldmatrix row in group

    // ldmatrix per-lane byte offsets (within a plane/tile)
    const uint32_t aoff = ((wm + (lg & 1) * 8 + lr) * A_ROW_STRIDE + (lg >> 1) * 4) * 4;
    const uint32_t boff = ((wn + (lg >> 1) * 8 + lr) * A_ROW_STRIDE + (lg & 1) * 4) * 4;

    // ---- register-thin producer mappings ----
    const int ch    = tid & 3;
    const int arow0 = (tid >> 2) & 63;
    const int bt0   = tid >> 7;              // B plane (0=hi, 1=lo)
    const int bnr   = (tid >> 2) & 31;       // B n row

    const __nv_bfloat16* aP0 = Ahi + (size_t)(bm0 + arow0) * KP + ch * 8;   // plane hi
    const __nv_bfloat16* aP1 = Alo + (size_t)(bm0 + arow0) * KP + ch * 8;   // plane lo
    const __nv_bfloat16* bP  = (bt0 ? Blo : Bhi) + (size_t)(bn0 + bnr) * KP + ch * 8;

    const uint32_t aD = sbase + (arow0 * A_ROW_STRIDE + ch * 4) * 4;
    const uint32_t bD = sbase + (OFF_B_U32 + bt0 * B_TILE + bnr * A_ROW_STRIDE + ch * 4) * 4;

    #define CP_TILE(db)                                                          \
        do {                                                                     \
            cp16(aD + (db), aP0);                                                \
            cp16(aD + (db) + 64 * A_ROW_STRIDE * 4, aP0 + (size_t)64 * KP);      \
            cp16(aD + (db) + A_PLANE * 4, aP1);                                  \
            cp16(aD + (db) + A_PLANE * 4 + 64 * A_ROW_STRIDE * 4,                \
                 aP1 + (size_t)64 * KP);                                         \
            cp16(bD + (db) + 0 * 2 * B_TILE * 4, bP + (size_t)0 * HID * KP);     \
            cp16(bD + (db) + 1 * 2 * B_TILE * 4, bP + (size_t)1 * HID * KP);     \
            cp16(bD + (db) + 2 * 2 * B_TILE * 4, bP + (size_t)2 * HID * KP);     \
            cp16(bD + (db) + 3 * 2 * B_TILE * 4, bP + (size_t)3 * HID * KP);     \
        } while (0)

    float acc[4][2][2][4];                  // [op][mf][nf][c]
    #pragma unroll
    for (int o = 0; o < 4; o++)
        #pragma unroll
        for (int mf = 0; mf < 2; mf++)
            #pragma unroll
            for (int nf = 0; nf < 2; nf++)
                #pragma unroll
                for (int c = 0; c < 4; c++) acc[o][mf][nf][c] = 0.f;

    constexpr int nk = KP / BK;

    // prologue: fill buffer 0
    CP_TILE(0);
    cp_commit();
    cp_wait0();
    __syncthreads();

    #pragma unroll 1
    for (int kt = 0; kt < nk; kt++) {
        const int cur  = kt & 1;
        const bool more = (kt + 1 < nk);
        if (more) {
            aP0 += BK; aP1 += BK; bP += BK;
            CP_TILE((cur ^ 1) * BUF_BYTES);
            cp_commit();
        }

        const uint32_t bufA = sbase + cur * BUF_BYTES;
        const uint32_t bufB = bufA + OFF_B_U32 * 4;
        #pragma unroll
        for (int kp = 0; kp < 2; kp++) {
            uint32_t afr[2][2][4];    // [plane][mf][a0..a3]
            #pragma unroll
            for (int pl = 0; pl < 2; pl++)
                #pragma unroll
                for (int mf = 0; mf < 2; mf++)
                    ldmx4(afr[pl][mf],
                          bufA + pl * (A_PLANE * 4) + aoff + mf * (16 * A_ROW_STRIDE * 4) + kp * 32);
            #pragma unroll
            for (int op = 0; op < 4; op++) {
                uint32_t bfrg[2][4];  // [plane][nf0b0, nf0b1, nf1b0, nf1b1]
                #pragma unroll
                for (int pl = 0; pl < 2; pl++)
                    ldmx4(bfrg[pl],
                          bufB + (op * 2 + pl) * (B_TILE * 4) + boff + kp * 32);
                // term-ordered issue: accumulator reuse distance 4 independent HMMAs
                #pragma unroll
                for (int mf = 0; mf < 2; mf++)
                    #pragma unroll
                    for (int nf = 0; nf < 2; nf++)
                        mma16816(acc[op][mf][nf], afr[0][mf], bfrg[0][nf*2], bfrg[0][nf*2+1]);
                #pragma unroll
                for (int mf = 0; mf < 2; mf++)
                    #pragma unroll
                    for (int nf = 0; nf < 2; nf++)
                        mma16816(acc[op][mf][nf], afr[0][mf], bfrg[1][nf*2], bfrg[1][nf*2+1]);
                #pragma unroll
                for (int mf = 0; mf < 2; mf++)
                    #pragma unroll
                    for (int nf = 0; nf < 2; nf++)
                        mma16816(acc[op][mf][nf], afr[1][mf], bfrg[0][nf*2], bfrg[0][nf*2+1]);
            }
        }
        if (more) {
            cp_wait0();
            __syncthreads();
        }
    }
    #undef CP_TILE

    // ---- epilogue: bias + act + z-weighted op-sum, RMW into g_acc; when this
    //      stage finalizes node i == stage+1 (<=4), also emit bf16 split planes.
    const float z0 = zp[0], z1 = zp[1], z2 = zp[2], z3 = zp[3];
    const bool emit_split = (i == stage + 1) && (i <= 4);
    uint32_t* sp_hi = (uint32_t*)(g_a_hi + (size_t)(i - 1) * BATCH * HID);
    uint32_t* sp_lo = (uint32_t*)(g_a_lo + (size_t)(i - 1) * BATCH * HID);

    #pragma unroll
    for (int mf = 0; mf < 2; mf++)
        #pragma unroll
        for (int nf = 0; nf < 2; nf++) {
            const int n0 = bn0 + wn + nf * 8 + qk * 2;
            float bv[4][2];
            #pragma unroll
            for (int op = 0; op < 4; op++) {
                bv[op][0] = bias[op * HID + n0];
                bv[op][1] = bias[op * HID + n0 + 1];
            }
            #pragma unroll
            for (int half = 0; half < 2; half++) {
                const int m = bm0 + wm + mf * 16 + qr + half * 8;
                float r0 = 0.f, r1 = 0.f;
                #pragma unroll
                for (int op = 0; op < 4; op++) {
                    const float p0 = acc[op][mf][nf][half * 2 + 0] + bv[op][0];
                    const float p1 = acc[op][mf][nf][half * 2 + 1] + bv[op][1];
                    float a0, a1;
                    switch (op) {
                        case 0:  a0 = tanhf(p0);                      a1 = tanhf(p1);                      break;
                        case 1:  a0 = fmaxf(p0, 0.f);                 a1 = fmaxf(p1, 0.f);                 break;
                        case 2:  a0 = p0 > 0.f ? p0 : expm1f(p0);     a1 = p1 > 0.f ? p1 : expm1f(p1);     break;
                        default: a0 = p0 > 0.f ? p0 : 0.01f * p0;     a1 = p1 > 0.f ? p1 : 0.01f * p1;     break;
                    }
                    const float zv = (op == 0) ? z0 : (op == 1) ? z1 : (op == 2) ? z2 : z3;
                    r0 += zv * a0; r1 += zv * a1;
                }
                float* dst = accOut + (size_t)m * HID + n0;
                if (stage != 0) {
                    float2 old = *reinterpret_cast<const float2*>(dst);
                    r0 += old.x; r1 += old.y;
                }
                float2 res; res.x = r0; res.y = r1;
                *reinterpret_cast<float2*>(dst) = res;
                if (emit_split) {
                    __nv_bfloat16 h0, l0, h1, l1;
                    bf16split(r0, h0, l0);
                    bf16split(r1, h1, l1);
                    const size_t widx = ((size_t)m * HID + n0) >> 1;
                    sp_hi[widx] = packbf2(h0, h1);
                    sp_lo[widx] = packbf2(l0, l1);
                }
            }
        }
}

// ---------------------------------------------------------------------------
// out = tanh(acc5 @ Wout + bout)
// ---------------------------------------------------------------------------
__global__ void out_kernel(const float* __restrict__ Wout,
                           const float* __restrict__ bout,
                           float* __restrict__ out)
{
    const int gw   = (blockIdx.x * blockDim.x + threadIdx.x) >> 5;
    const int lane = threadIdx.x & 31;
    if (gw >= BATCH) return;
    const float* a = g_acc + (size_t)4 * BATCH * HID + (size_t)gw * HID;

    float s[NOUT];
    #pragma unroll
    for (int n = 0; n < NOUT; n++) s[n] = 0.f;
    for (int kk = lane; kk < HID; kk += 32) {
        const float av = a[kk];
        const float* wr = Wout + (size_t)kk * NOUT;
        #pragma unroll
        for (int n = 0; n < NOUT; n++) s[n] = fmaf(av, wr[n], s[n]);
    }
    #pragma unroll
    for (int off = 16; off; off >>= 1)
        #pragma unroll
        for (int n = 0; n < NOUT; n++)
            s[n] += __shfl_down_sync(0xffffffffu, s[n], off);
    if (lane == 0) {
        #pragma unroll
        for (int n = 0; n < NOUT; n++)
            out[(size_t)gw * NOUT + n] = tanhf(s[n] + bout[n]);
    }
}

// ---------------------------------------------------------------------------
extern "C" void kernel_launch(void* const* d_in, const int* in_sizes, int n_in,
                              void* d_out, int out_size)
{
    const float* x    = (const float*)d_in[0];
    const float* W0   = (const float*)d_in[1];
    const float* b0   = (const float*)d_in[2];
    const float* Wh   = (const float*)d_in[3];
    const float* bh   = (const float*)d_in[4];
    const float* Wout = (const float*)d_in[5];
    const float* bout = (const float*)d_in[6];
    const float* la   = (const float*)d_in[7];
    const float* eps  = (const float*)d_in[8];
    float* out = (float*)d_out;

    cudaFuncSetAttribute(stage_mma_kernel<KP0>,
                         cudaFuncAttributeMaxDynamicSharedMemorySize, SMEM_BYTES);
    cudaFuncSetAttribute(stage_mma_kernel<HID>,
                         cudaFuncAttributeMaxDynamicSharedMemorySize, SMEM_BYTES);

    prepass_kernel<<<PRE_TOTAL, 256>>>(la, eps, x, W0);
    // stage 0: 1D grid, 2560 mma blocks + 512 interleaved split_th blocks
    stage_mma_kernel<KP0><<<3072, NTHREADS, SMEM_BYTES>>>(0, b0, bh, Wh);
    for (int k = 1; k < 5; k++) {
        dim3 grid(BATCH / BM, HID / BN, 5 - k);
        stage_mma_kernel<HID><<<grid, NTHREADS, SMEM_BYTES>>>(k, b0, bh, Wh);
    }
    out_kernel<<<(BATCH * 32) / 256, 256>>>(Wout, bout, out);
}

// round 16
// speedup vs baseline: 1.4745x; 1.4745x over previous
#include <cuda_runtime.h>
#include <cuda_bf16.h>
#include <math.h>
#include <stdint.h>

#define BATCH   2048
#define IN_DIM  376
#define HID     1024
#define NOUT    17
#define NCELLS  6
#define NOPS    5
#define KP0     384            // IN_DIM padded to multiple of BK

#define BM 128
#define BN 32
#define BK 32
#define NTHREADS 256

// smem per kt buffer: A frags 16KB (8 mtiles x 4 s x 32 lanes x 16B),
//                     B frags 16KB (4 op x 4 ntile x 2 spair x 32 x 16B)
#define A_KT_BYTES 16384
#define B_KT_BYTES 16384
#define BUF_BYTES  (A_KT_BYTES + B_KT_BYTES)   // 32 KB
#define SMEM_BYTES (2 * BUF_BYTES)             // 64 KB (2 CTAs/SM)

// ---------------------------------------------------------------------------
// device scratch (all fp32, tf32-rounded, fragment-packed)
// ---------------------------------------------------------------------------
__device__ float g_acc[5u * BATCH * HID];
__device__ float g_z[150];
__device__ float g_w0[20u * HID * KP0];          // stage-0 weights, frag layout
__device__ float g_wh[40u * HID * HID];          // hidden weights, frag layout
__device__ float g_xf[(size_t)BATCH * KP0];      // x, A-frag layout
__device__ float g_af[4u * BATCH * HID];         // node 1..4 activations, A-frag layout

// ---------------------------------------------------------------------------
__device__ __forceinline__ float tf32r(float a) {
    uint32_t u; asm("cvt.rna.tf32.f32 %0, %1;" : "=r"(u) : "f"(a));
    return __uint_as_float(u);
}
__device__ __forceinline__ uint32_t smem_u32(const void* p) {
    uint32_t a;
    asm("{ .reg .u64 t; cvta.to.shared.u64 t, %1; cvt.u32.u64 %0, t; }"
        : "=r"(a) : "l"(p));
    return a;
}
__device__ __forceinline__ void lds128(uint4& v, uint32_t addr) {
    asm volatile("ld.shared.v4.b32 {%0,%1,%2,%3}, [%4];"
        : "=r"(v.x), "=r"(v.y), "=r"(v.z), "=r"(v.w) : "r"(addr));
}
__device__ __forceinline__ void cp16(uint32_t dst, const void* src) {
    asm volatile("cp.async.cg.shared.global [%0], [%1], 16;" :: "r"(dst), "l"(src));
}
__device__ __forceinline__ void cp_commit() { asm volatile("cp.async.commit_group;"); }
__device__ __forceinline__ void cp_wait0()  { asm volatile("cp.async.wait_group 0;" ::: "memory"); }

// m16n8k8 tf32 MMA. A: a0(row g, col t), a1(g+8, t), a2(g, t+4), a3(g+8, t+4)
//                   B: b0(k=t, n=g), b1(k=t+4, n=g);  D rows g/g+8, cols 2t,2t+1
__device__ __forceinline__ void mma_tf32(float* d, const uint4& a,
                                         uint32_t b0, uint32_t b1) {
    asm volatile(
        "mma.sync.aligned.m16n8k8.row.col.f32.tf32.tf32.f32 "
        "{%0,%1,%2,%3}, {%4,%5,%6,%7}, {%8,%9}, {%0,%1,%2,%3};\n"
        : "+f"(d[0]), "+f"(d[1]), "+f"(d[2]), "+f"(d[3])
        : "r"(a.x), "r"(a.y), "r"(a.z), "r"(a.w), "r"(b0), "r"(b1));
}

// A-fragment flat index for logical element (m, k), K = row length.
// layout: [m/16][k/8][lane][j], lane = (m%8)*4 + (k%4), j = ((m/8)%2) + 2*((k/4)%2)
__device__ __forceinline__ size_t a_frag_idx(int m, int k, int K) {
    const int lane = (m & 7) * 4 + (k & 3);
    const int j    = ((m >> 3) & 1) + 2 * ((k >> 2) & 1);
    return ((size_t)(m >> 4) * (K >> 3) + (k >> 3)) * 128 + lane * 4 + j;
}

// edge -> (source stage s, target i) map for Wh
__device__ __forceinline__ void pair_to_edge(int e, int& s, int& i) {
    if      (e < 4) { s = 1; i = e + 2; }
    else if (e < 7) { s = 2; i = e - 4 + 3; }
    else if (e < 9) { s = 3; i = e - 7 + 4; }
    else            { s = 4; i = 5; }
}

// ---------------------------------------------------------------------------
// z = softmax(log_alphas + eps) over op axis (TAU = 1)
// ---------------------------------------------------------------------------
__global__ void z_kernel(const float* __restrict__ la, const float* __restrict__ eps) {
    int t = threadIdx.x;
    if (t < 30) {
        float v[NOPS], mx = -1e30f;
        #pragma unroll
        for (int o = 0; o < NOPS; o++) { v[o] = la[t*NOPS+o] + eps[t*NOPS+o]; mx = fmaxf(mx, v[o]); }
        float s = 0.f;
        #pragma unroll
        for (int o = 0; o < NOPS; o++) { v[o] = expf(v[o] - mx); s += v[o]; }
        float inv = 1.f / s;
        #pragma unroll
        for (int o = 0; o < NOPS; o++) g_z[t*NOPS+o] = v[o] * inv;
    }
}

// ---------------------------------------------------------------------------
// Pre-pass: x -> tf32-rounded A-fragment layout (zero-padded to KP0)
// ---------------------------------------------------------------------------
__global__ void split_x_kernel(const float* __restrict__ x) {
    const int idx = blockIdx.x * 256 + threadIdx.x;     // [0, BATCH*KP0)
    const int m = idx / KP0, k = idx % KP0;
    float v = (k < IN_DIM) ? x[(size_t)m * IN_DIM + k] : 0.f;
    g_xf[a_frag_idx(m, k, KP0)] = tf32r(v);
}

// ---------------------------------------------------------------------------
// Pre-pass weights: one block = one (pair, nb, kt) 32n x 32k tile.
// Stages source W[k][n] (n-stride HID), emits B-fragment chunks:
// chunk = [nb][kt][ntile][sp][lane] of 4 floats {b0(s0),b1(s0),b0(s1),b1(s1)}
// where within chunk: s_loc = sp*2 + jp/2, k = s_loc*8 + (lane%4) + (jp%2)*4,
//                     n = ntile*8 + lane/4.
// ---------------------------------------------------------------------------
template<int K>
__device__ __forceinline__ void split_w_tile(const float* __restrict__ src,
                                             float* __restrict__ dst,
                                             int nb, int kt, int kd_limit)
{
    __shared__ float t[32][33];
    const int tid = threadIdx.x;
    const int tk = tid >> 5, tn = tid & 31;
    #pragma unroll
    for (int r = 0; r < 4; r++) {
        const int k = tk + r * 8;
        const int gk = kt * 32 + k;
        t[k][tn] = (gk < kd_limit) ? src[(size_t)gk * HID + nb * 32 + tn] : 0.f;
    }
    __syncthreads();
    const int nt = tid >> 6, sp = (tid >> 5) & 1, lane = tid & 31;
    float4 v;
    #pragma unroll
    for (int jp = 0; jp < 4; jp++) {
        const int sl = sp * 2 + (jp >> 1);
        const int kk = sl * 8 + (lane & 3) + (jp & 1) * 4;
        const int nn = nt * 8 + (lane >> 2);
        ((float*)&v)[jp] = tf32r(t[kk][nn]);
    }
    const size_t chunk = ((size_t)(nb * (K / 32) + kt) * 8 + (nt * 2 + sp)) * 32 + lane;
    *reinterpret_cast<float4*>(dst + chunk * 4) = v;
}

__global__ void split_t0_kernel(const float* __restrict__ W0) {
    const int b = blockIdx.x;                   // 20 * 32 * 12
    const int pair = b / (32 * 12);
    const int rem  = b % (32 * 12);
    const int nb = rem / 12, kt = rem % 12;
    const int i = (pair >> 2) + 1, op = pair & 3;
    const float* src = W0 + ((size_t)(i * NOPS + op)) * IN_DIM * HID;
    split_w_tile<KP0>(src, g_w0 + (size_t)pair * HID * KP0, nb, kt, IN_DIM);
}

__global__ void split_th_kernel(const float* __restrict__ Wh) {
    const int b = blockIdx.x;                   // 40 * 32 * 32
    const int pair = b / 1024;
    const int nb = (b >> 5) & 31, kt = b & 31;
    int s, i; pair_to_edge(pair >> 2, s, i);
    const int op = pair & 3;
    const float* src = Wh + ((size_t)(((s - 1) * NCELLS + i) * NOPS + op)) * HID * HID;
    split_w_tile<HID>(src, g_wh + (size_t)pair * HID * HID, nb, kt, HID);
}

// ---------------------------------------------------------------------------
// Stage GEMM: single-pass tf32 mma.sync m16n8k8; operands pre-packed in
// fragment order -> cp.async straight copy + conflict-free LDS.128 loads.
// CTA = [128 x 32] x 4 ops; warp = 32x16; 2 CTAs/SM.
// grid = (BATCH/BM, HID/BN, targets)
// ---------------------------------------------------------------------------
template<int K>
__global__ __launch_bounds__(NTHREADS, 2)
void stage_mma_kernel(int stage, const float* __restrict__ b0,
                      const float* __restrict__ bh)
{
    extern __shared__ uint32_t smem[];
    const uint32_t sbase = smem_u32(smem);
    const int tid = threadIdx.x;
    const int i   = stage + 1 + blockIdx.z;
    const int bm0 = blockIdx.x * BM;
    const int bn0 = blockIdx.y * BN;

    const float *Abase, *Wbase, *bias;
    if (stage == 0) {
        Abase = g_xf;
        Wbase = g_w0 + (size_t)((i - 1) * 4) * HID * K;
        bias  = b0 + (size_t)(i * NOPS) * HID;
    } else {
        Abase = g_af + (size_t)(stage - 1) * BATCH * HID;
        static const int eoff[5] = {0, 0, 4, 7, 9};
        const int e = eoff[stage] + (i - stage - 1);
        Wbase = g_wh + (size_t)(e * 4) * HID * K;
        bias  = bh + (size_t)(((stage - 1) * NCELLS + i) * NOPS) * HID;
    }
    float* accOut = g_acc + (size_t)(i - 1) * BATCH * HID;
    const float* zp = g_z + (stage * NCELLS + i) * NOPS;

    const int w    = tid >> 5, lane = tid & 31;
    const int qr   = lane >> 2;             // t/4
    const int qk   = lane & 3;              // t%4
    const int wmt  = (w & 3) * 2;           // warp base mtile (of 8 local)
    const int wnt  = (w >> 2) * 2;          // warp base ntile (of 4 local)

    // ---- producers: straight fragment copy ----
    const int hi = tid >> 7;                // A: mtile parity
    const int sl = (tid >> 5) & 3;          // A: s within kt
    const float* aP = Abase + (((size_t)(bm0 >> 4) + hi) * (K / 8) + sl) * 128 + lane * 4;
    const float* bP = Wbase + ((size_t)(bn0 >> 5) * (K / 32) * 8 + (tid >> 5)) * 128 + lane * 4;
    const uint32_t aD = sbase + tid * 16;
    const uint32_t bD = sbase + A_KT_BYTES + tid * 16;

    #define CP_TILE(db)                                                       \
        do {                                                                  \
            cp16(aD + (db) + 0 * 4096, aP + (size_t)0 * (K * 32));            \
            cp16(aD + (db) + 1 * 4096, aP + (size_t)1 * (K * 32));            \
            cp16(aD + (db) + 2 * 4096, aP + (size_t)2 * (K * 32));            \
            cp16(aD + (db) + 3 * 4096, aP + (size_t)3 * (K * 32));            \
            cp16(bD + (db) + 0 * 4096, bP + (size_t)0 * HID * K);             \
            cp16(bD + (db) + 1 * 4096, bP + (size_t)1 * HID * K);             \
            cp16(bD + (db) + 2 * 4096, bP + (size_t)2 * HID * K);             \
            cp16(bD + (db) + 3 * 4096, bP + (size_t)3 * HID * K);             \
        } while (0)

    float acc[4][2][2][4];                  // [op][mf][nf][c]
    #pragma unroll
    for (int o = 0; o < 4; o++)
        #pragma unroll
        for (int mf = 0; mf < 2; mf++)
            #pragma unroll
            for (int nf = 0; nf < 2; nf++)
                #pragma unroll
                for (int c = 0; c < 4; c++) acc[o][mf][nf][c] = 0.f;

    constexpr int nk = K / BK;

    CP_TILE(0);
    cp_commit();
    cp_wait0();
    __syncthreads();

    #pragma unroll 1
    for (int kt = 0; kt < nk; kt++) {
        const int cur  = kt & 1;
        const bool more = (kt + 1 < nk);
        if (more) {
            aP += 512; bP += 1024;
            CP_TILE((cur ^ 1) * BUF_BYTES);
            cp_commit();
        }

        const uint32_t bufA = sbase + cur * BUF_BYTES;
        const uint32_t bufB = bufA + A_KT_BYTES;
        #pragma unroll
        for (int sp = 0; sp < 2; sp++) {
            uint4 bf[4][2];                 // [op][nf] = {b0s0,b1s0,b0s1,b1s1}
            #pragma unroll
            for (int op = 0; op < 4; op++)
                #pragma unroll
                for (int nf = 0; nf < 2; nf++)
                    lds128(bf[op][nf],
                           bufB + (((op * 4 + wnt + nf) * 2 + sp) * 32 + lane) * 16);
            #pragma unroll
            for (int sh = 0; sh < 2; sh++) {
                const int s = sp * 2 + sh;
                uint4 af[2];
                #pragma unroll
                for (int mf = 0; mf < 2; mf++)
                    lds128(af[mf], bufA + (((wmt + mf) * 4 + s) * 32 + lane) * 16);
                #pragma unroll
                for (int op = 0; op < 4; op++)
                    #pragma unroll
                    for (int mf = 0; mf < 2; mf++)
                        #pragma unroll
                        for (int nf = 0; nf < 2; nf++) {
                            const uint32_t b0v = sh ? bf[op][nf].z : bf[op][nf].x;
                            const uint32_t b1v = sh ? bf[op][nf].w : bf[op][nf].y;
                            mma_tf32(acc[op][mf][nf], af[mf], b0v, b1v);
                        }
            }
        }
        if (more) {
            cp_wait0();
            __syncthreads();
        }
    }
    #undef CP_TILE

    // ---- epilogue: bias + act + z-weighted op-sum, RMW into g_acc; when this
    //      stage finalizes node i == stage+1 (<=4), emit tf32 A-fragments.
    const float z0 = zp[0], z1 = zp[1], z2 = zp[2], z3 = zp[3];
    const bool emit_split = (i == stage + 1) && (i <= 4);
    float* afOut = g_af + (size_t)(i - 1) * BATCH * HID;
    const int wm = (w & 3) * 32;
    const int wn = (w >> 2) * 16;

    #pragma unroll
    for (int mf = 0; mf < 2; mf++)
        #pragma unroll
        for (int nf = 0; nf < 2; nf++) {
            const int n0 = bn0 + wn + nf * 8 + qk * 2;
            float bv[4][2];
            #pragma unroll
            for (int op = 0; op < 4; op++) {
                bv[op][0] = bias[op * HID + n0];
                bv[op][1] = bias[op * HID + n0 + 1];
            }
            #pragma unroll
            for (int half = 0; half < 2; half++) {
                const int m = bm0 + wm + mf * 16 + qr + half * 8;
                float r0 = 0.f, r1 = 0.f;
                #pragma unroll
                for (int op = 0; op < 4; op++) {
                    const float p0 = acc[op][mf][nf][half * 2 + 0] + bv[op][0];
                    const float p1 = acc[op][mf][nf][half * 2 + 1] + bv[op][1];
                    float a0, a1;
                    switch (op) {
                        case 0:  a0 = tanhf(p0);                      a1 = tanhf(p1);                      break;
                        case 1:  a0 = fmaxf(p0, 0.f);                 a1 = fmaxf(p1, 0.f);                 break;
                        case 2:  a0 = p0 > 0.f ? p0 : expm1f(p0);     a1 = p1 > 0.f ? p1 : expm1f(p1);     break;
                        default: a0 = p0 > 0.f ? p0 : 0.01f * p0;     a1 = p1 > 0.f ? p1 : 0.01f * p1;     break;
                    }
                    const float zv = (op == 0) ? z0 : (op == 1) ? z1 : (op == 2) ? z2 : z3;
                    r0 += zv * a0; r1 += zv * a1;
                }
                float* dst = accOut + (size_t)m * HID + n0;
                if (stage != 0) {
                    float2 old = *reinterpret_cast<const float2*>(dst);
                    r0 += old.x; r1 += old.y;
                }
                float2 res; res.x = r0; res.y = r1;
                *reinterpret_cast<float2*>(dst) = res;
                if (emit_split) {
                    afOut[a_frag_idx(m, n0,     HID)] = tf32r(r0);
                    afOut[a_frag_idx(m, n0 + 1, HID)] = tf32r(r1);
                }
            }
        }
}

// ---------------------------------------------------------------------------
// out = tanh(acc5 @ Wout + bout)
// ---------------------------------------------------------------------------
__global__ void out_kernel(const float* __restrict__ Wout,
                           const float* __restrict__ bout,
                           float* __restrict__ out)
{
    const int gw   = (blockIdx.x * blockDim.x + threadIdx.x) >> 5;
    const int lane = threadIdx.x & 31;
    if (gw >= BATCH) return;
    const float* a = g_acc + (size_t)4 * BATCH * HID + (size_t)gw * HID;

    float s[NOUT];
    #pragma unroll
    for (int n = 0; n < NOUT; n++) s[n] = 0.f;
    for (int kk = lane; kk < HID; kk += 32) {
        const float av = a[kk];
        const float* wr = Wout + (size_t)kk * NOUT;
        #pragma unroll
        for (int n = 0; n < NOUT; n++) s[n] = fmaf(av, wr[n], s[n]);
    }
    #pragma unroll
    for (int off = 16; off; off >>= 1)
        #pragma unroll
        for (int n = 0; n < NOUT; n++)
            s[n] += __shfl_down_sync(0xffffffffu, s[n], off);
    if (lane == 0) {
        #pragma unroll
        for (int n = 0; n < NOUT; n++)
            out[(size_t)gw * NOUT + n] = tanhf(s[n] + bout[n]);
    }
}

// ---------------------------------------------------------------------------
extern "C" void kernel_launch(void* const* d_in, const int* in_sizes, int n_in,
                              void* d_out, int out_size)
{
    const float* x    = (const float*)d_in[0];
    const float* W0   = (const float*)d_in[1];
    const float* b0   = (const float*)d_in[2];
    const float* Wh   = (const float*)d_in[3];
    const float* bh   = (const float*)d_in[4];
    const float* Wout = (const float*)d_in[5];
    const float* bout = (const float*)d_in[6];
    const float* la   = (const float*)d_in[7];
    const float* eps  = (const float*)d_in[8];
    float* out = (float*)d_out;

    cudaFuncSetAttribute(stage_mma_kernel<KP0>,
                         cudaFuncAttributeMaxDynamicSharedMemorySize, SMEM_BYTES);
    cudaFuncSetAttribute(stage_mma_kernel<HID>,
                         cudaFuncAttributeMaxDynamicSharedMemorySize, SMEM_BYTES);

    z_kernel<<<1, 32>>>(la, eps);
    split_x_kernel<<<(BATCH * KP0) / 256, 256>>>(x);
    split_t0_kernel<<<20 * 32 * 12, 256>>>(W0);
    split_th_kernel<<<40 * 32 * 32, 256>>>(Wh);
    for (int k = 0; k < 5; k++) {
        dim3 grid(BATCH / BM, HID / BN, 5 - k);
        if (k == 0)
            stage_mma_kernel<KP0><<<grid, NTHREADS, SMEM_BYTES>>>(k, b0, bh);
        else
            stage_mma_kernel<HID><<<grid, NTHREADS, SMEM_BYTES>>>(k, b0, bh);
    }
    out_kernel<<<(BATCH * 32) / 256, 256>>>(Wout, bout, out);
}

// round 17
// speedup vs baseline: 2.4934x; 1.6910x over previous
#include <cuda_runtime.h>
#include <cuda_fp16.h>
#include <math.h>
#include <stdint.h>

#define BATCH   2048
#define IN_DIM  376
#define HID     1024
#define NOUT    17
#define NCELLS  6
#define NOPS    5
#define KP0     384            // IN_DIM padded to multiple of BK

#define BM 128
#define BN 32
#define BK 32
#define NTHREADS 256

// smem per kt buffer: A frags 8KB (8 mtiles x 2 ks x 32 lanes x 16B),
//                     B frags 8KB (4 op x 2 ks x 2 npair x 32 lanes x 16B)
#define A_KT_BYTES 8192
#define B_KT_BYTES 8192
#define BUF_BYTES  (A_KT_BYTES + B_KT_BYTES)   // 16 KB
#define SMEM_BYTES (2 * BUF_BYTES)             // 32 KB (2 CTAs/SM)

// ---------------------------------------------------------------------------
// device scratch
// ---------------------------------------------------------------------------
__device__ float g_acc[5u * BATCH * HID];
__device__ float g_z[150];
__device__ __half g_w0[20u * HID * KP0];         // stage-0 weights, B-frag fp16
__device__ __half g_wh[40u * HID * HID];         // hidden weights, B-frag fp16
__device__ __half g_xf[(size_t)BATCH * KP0];     // x, A-frag fp16
__device__ __half g_af[4u * BATCH * HID];        // node 1..4 activations, A-frag fp16

// ---------------------------------------------------------------------------
__device__ __forceinline__ uint32_t smem_u32(const void* p) {
    uint32_t a;
    asm("{ .reg .u64 t; cvta.to.shared.u64 t, %1; cvt.u32.u64 %0, t; }"
        : "=r"(a) : "l"(p));
    return a;
}
__device__ __forceinline__ void lds128(uint4& v, uint32_t addr) {
    asm volatile("ld.shared.v4.b32 {%0,%1,%2,%3}, [%4];"
        : "=r"(v.x), "=r"(v.y), "=r"(v.z), "=r"(v.w) : "r"(addr));
}
__device__ __forceinline__ void cp16(uint32_t dst, const void* src) {
    asm volatile("cp.async.cg.shared.global [%0], [%1], 16;" :: "r"(dst), "l"(src));
}
__device__ __forceinline__ void cp_commit() { asm volatile("cp.async.commit_group;"); }
__device__ __forceinline__ void cp_wait0()  { asm volatile("cp.async.wait_group 0;" ::: "memory"); }

// fp16 m16n8k16, fp32 accum.
// A regs: a0=(g, k0,k0+1) a1=(g+8, k0..) a2=(g, k0+8..) a3=(g+8, k0+8..), k0=(t%4)*2
// B regs: b0=(k0.., n=t/4) b1=(k0+8.., n)
__device__ __forceinline__ void mma_f16(float* d, const uint4& a,
                                        uint32_t b0, uint32_t b1) {
    asm volatile(
        "mma.sync.aligned.m16n8k16.row.col.f32.f16.f16.f32 "
        "{%0,%1,%2,%3}, {%4,%5,%6,%7}, {%8,%9}, {%0,%1,%2,%3};\n"
        : "+f"(d[0]), "+f"(d[1]), "+f"(d[2]), "+f"(d[3])
        : "r"(a.x), "r"(a.y), "r"(a.z), "r"(a.w), "r"(b0), "r"(b1));
}

// A-fragment flat half index for logical (m, k), row length K.
// [m/16][k/16][lane][reg][h]: lane=(m%8)*4+((k%8)/2), reg=((m/8)%2)+2*((k%16)/8), h=k%2
__device__ __forceinline__ size_t a_frag_idx16(int m, int k, int K) {
    const int lane = (m & 7) * 4 + ((k & 7) >> 1);
    const int reg  = ((m >> 3) & 1) + 2 * ((k >> 3) & 1);
    return ((size_t)(m >> 4) * (K >> 4) + (k >> 4)) * 256 + lane * 8 + reg * 2 + (k & 1);
}

// edge -> (source stage s, target i) map for Wh
__device__ __forceinline__ void pair_to_edge(int e, int& s, int& i) {
    if      (e < 4) { s = 1; i = e + 2; }
    else if (e < 7) { s = 2; i = e - 4 + 3; }
    else if (e < 9) { s = 3; i = e - 7 + 4; }
    else            { s = 4; i = 5; }
}

// ---------------------------------------------------------------------------
// z = softmax(log_alphas + eps) over op axis (TAU = 1)
// ---------------------------------------------------------------------------
__global__ void z_kernel(const float* __restrict__ la, const float* __restrict__ eps) {
    int t = threadIdx.x;
    if (t < 30) {
        float v[NOPS], mx = -1e30f;
        #pragma unroll
        for (int o = 0; o < NOPS; o++) { v[o] = la[t*NOPS+o] + eps[t*NOPS+o]; mx = fmaxf(mx, v[o]); }
        float s = 0.f;
        #pragma unroll
        for (int o = 0; o < NOPS; o++) { v[o] = expf(v[o] - mx); s += v[o]; }
        float inv = 1.f / s;
        #pragma unroll
        for (int o = 0; o < NOPS; o++) g_z[t*NOPS+o] = v[o] * inv;
    }
}

// ---------------------------------------------------------------------------
// Pre-pass: x -> fp16 A-fragment layout (zero-padded to KP0)
// ---------------------------------------------------------------------------
__global__ void split_x_kernel(const float* __restrict__ x) {
    const int idx = blockIdx.x * 256 + threadIdx.x;     // [0, BATCH*KP0)
    const int m = idx / KP0, k = idx % KP0;
    float v = (k < IN_DIM) ? x[(size_t)m * IN_DIM + k] : 0.f;
    g_xf[a_frag_idx16(m, k, KP0)] = __float2half_rn(v);
}

// ---------------------------------------------------------------------------
// Pre-pass weights: one block = one (pair, nb, kt) 32n x 32k tile.
// Source W[k][n] (n-stride HID); emit B-fragment chunks:
//   chunk c = ks*2+np at [nb][kt][c][lane], uint4 word j = (ntl*2+reg), halves h
//   n = np*16 + ntl*8 + lane/4,  k = ks*16 + reg*8 + (lane%4)*2 + h
// ---------------------------------------------------------------------------
template<int K>
__device__ __forceinline__ void split_w_tile(const float* __restrict__ src,
                                             __half* __restrict__ dst,
                                             int nb, int kt, int kd_limit)
{
    __shared__ float t[32][33];
    const int tid = threadIdx.x;
    const int tk = tid >> 5, tn = tid & 31;
    #pragma unroll
    for (int r = 0; r < 4; r++) {
        const int k = tk + r * 8;
        const int gk = kt * 32 + k;
        t[k][tn] = (gk < kd_limit) ? src[(size_t)gk * HID + nb * 32 + tn] : 0.f;
    }
    __syncthreads();
    if (tid < 128) {
        const int c = tid >> 5, lane = tid & 31;
        const int ks = c >> 1, np = c & 1;
        uint32_t wv[4];
        #pragma unroll
        for (int j = 0; j < 4; j++) {
            const int ntl = j >> 1, reg = j & 1;
            const int n = np * 16 + ntl * 8 + (lane >> 2);
            const int k = ks * 16 + reg * 8 + (lane & 3) * 2;
            __half2 h2(__float2half_rn(t[k][n]), __float2half_rn(t[k + 1][n]));
            wv[j] = *reinterpret_cast<uint32_t*>(&h2);
        }
        const size_t chunk = ((size_t)nb * (K / 32) + kt) * 4 + c;
        uint4 v; v.x = wv[0]; v.y = wv[1]; v.z = wv[2]; v.w = wv[3];
        *reinterpret_cast<uint4*>(dst + chunk * 256 + lane * 8) = v;
    }
}

__global__ void split_t0_kernel(const float* __restrict__ W0) {
    const int b = blockIdx.x;                   // 20 * 32 * 12
    const int pair = b / (32 * 12);
    const int rem  = b % (32 * 12);
    const int nb = rem / 12, kt = rem % 12;
    const int i = (pair >> 2) + 1, op = pair & 3;
    const float* src = W0 + ((size_t)(i * NOPS + op)) * IN_DIM * HID;
    split_w_tile<KP0>(src, g_w0 + (size_t)pair * HID * KP0, nb, kt, IN_DIM);
}

__global__ void split_th_kernel(const float* __restrict__ Wh) {
    const int b = blockIdx.x;                   // 40 * 32 * 32
    const int pair = b / 1024;
    const int nb = (b >> 5) & 31, kt = b & 31;
    int s, i; pair_to_edge(pair >> 2, s, i);
    const int op = pair & 3;
    const float* src = Wh + ((size_t)(((s - 1) * NCELLS + i) * NOPS + op)) * HID * HID;
    split_w_tile<HID>(src, g_wh + (size_t)pair * HID * HID, nb, kt, HID);
}

// ---------------------------------------------------------------------------
// Stage GEMM: single-pass fp16 mma.sync m16n8k16; operands fragment-packed
// in gmem -> cp.async straight copy + conflict-free LDS.128.
// CTA = [128 x 32] x 4 ops; warp = 32x16; 2 CTAs/SM.
// grid = (BATCH/BM, HID/BN, targets)
// ---------------------------------------------------------------------------
template<int K>
__global__ __launch_bounds__(NTHREADS, 2)
void stage_mma_kernel(int stage, const float* __restrict__ b0,
                      const float* __restrict__ bh)
{
    extern __shared__ uint32_t smem[];
    const uint32_t sbase = smem_u32(smem);
    const int tid = threadIdx.x;
    const int i   = stage + 1 + blockIdx.z;
    const int bm0 = blockIdx.x * BM;
    const int bn0 = blockIdx.y * BN;

    const __half *Abase, *Wbase;
    const float* bias;
    if (stage == 0) {
        Abase = g_xf;
        Wbase = g_w0 + (size_t)((i - 1) * 4) * HID * K;
        bias  = b0 + (size_t)(i * NOPS) * HID;
    } else {
        Abase = g_af + (size_t)(stage - 1) * BATCH * HID;
        static const int eoff[5] = {0, 0, 4, 7, 9};
        const int e = eoff[stage] + (i - stage - 1);
        Wbase = g_wh + (size_t)(e * 4) * HID * K;
        bias  = bh + (size_t)(((stage - 1) * NCELLS + i) * NOPS) * HID;
    }
    float* accOut = g_acc + (size_t)(i - 1) * BATCH * HID;
    const float* zp = g_z + (stage * NCELLS + i) * NOPS;

    const int w    = tid >> 5, lane = tid & 31;
    const int qr   = lane >> 2;             // t/4
    const int qk   = lane & 3;              // t%4
    const int wmt  = (w & 3) * 2;           // warp base mtile (of 8)
    const int wnp  = w >> 2;                // warp npair (0..1)

    // ---- producers: straight fragment copy, 4 cp16/thread/kt ----
    // A slots: s=tid (chunk 0..7), s=tid+256 (chunk 8..15); chunk = mt*2+ks
    const int amt = tid >> 6;               // mt for first slot (0..3)
    const int aks = (tid >> 5) & 1;
    const __half* aP = Abase + (((size_t)(bm0 >> 4) + amt) * (K >> 4) + aks) * 256 + (lane) * 8;
    // B slots: s=tid (op 0..1), s=tid+256 (op 2..3); within op: c = ks*2+np
    const int bop = tid >> 7;               // 0..1
    const int bc  = (tid & 127) >> 5;       // 0..3
    const __half* bP = Wbase + (size_t)bop * HID * K
                     + (((size_t)bn0 >> 5) * (K / 32) * 4 + bc) * 256 + lane * 8;
    const uint32_t aD = sbase + tid * 16;
    const uint32_t bD = sbase + A_KT_BYTES + tid * 16;

    #define CP_TILE(db)                                                       \
        do {                                                                  \
            cp16(aD + (db), aP);                                              \
            cp16(aD + (db) + 4096, aP + (size_t)64 * K);                      \
            cp16(bD + (db), bP);                                              \
            cp16(bD + (db) + 4096, bP + (size_t)2 * HID * K);                 \
        } while (0)

    float acc[4][2][2][4];                  // [op][mf][nf][c]
    #pragma unroll
    for (int o = 0; o < 4; o++)
        #pragma unroll
        for (int mf = 0; mf < 2; mf++)
            #pragma unroll
            for (int nf = 0; nf < 2; nf++)
                #pragma unroll
                for (int c = 0; c < 4; c++) acc[o][mf][nf][c] = 0.f;

    constexpr int nk = K / BK;

    CP_TILE(0);
    cp_commit();
    cp_wait0();
    __syncthreads();

    #pragma unroll 1
    for (int kt = 0; kt < nk; kt++) {
        const int cur  = kt & 1;
        const bool more = (kt + 1 < nk);
        if (more) {
            aP += 512; bP += 1024;
            CP_TILE((cur ^ 1) * BUF_BYTES);
            cp_commit();
        }

        const uint32_t bufA = sbase + cur * BUF_BYTES;
        const uint32_t bufB = bufA + A_KT_BYTES;
        #pragma unroll
        for (int ks = 0; ks < 2; ks++) {
            uint4 af[2];
            #pragma unroll
            for (int mf = 0; mf < 2; mf++)
                lds128(af[mf], bufA + (((wmt + mf) * 2 + ks) * 32 + lane) * 16);
            uint4 bf[4];                    // per op: {b0 nf0, b1 nf0, b0 nf1, b1 nf1}
            #pragma unroll
            for (int op = 0; op < 4; op++)
                lds128(bf[op], bufB + (((op * 2 + ks) * 2 + wnp) * 32 + lane) * 16);
            #pragma unroll
            for (int op = 0; op < 4; op++)
                #pragma unroll
                for (int mf = 0; mf < 2; mf++)
                    #pragma unroll
                    for (int nf = 0; nf < 2; nf++) {
                        const uint32_t b0v = nf ? bf[op].z : bf[op].x;
                        const uint32_t b1v = nf ? bf[op].w : bf[op].y;
                        mma_f16(acc[op][mf][nf], af[mf], b0v, b1v);
                    }
        }
        if (more) {
            cp_wait0();
            __syncthreads();
        }
    }
    #undef CP_TILE

    // ---- epilogue: bias + act + z-weighted op-sum, RMW into g_acc; when this
    //      stage finalizes node i == stage+1 (<=4), emit fp16 A-fragments.
    const float z0 = zp[0], z1 = zp[1], z2 = zp[2], z3 = zp[3];
    const bool emit_split = (i == stage + 1) && (i <= 4);
    __half* afOut = g_af + (size_t)(i - 1) * BATCH * HID;
    const int wm = (w & 3) * 32;
    const int wn = (w >> 2) * 16;

    #pragma unroll
    for (int mf = 0; mf < 2; mf++)
        #pragma unroll
        for (int nf = 0; nf < 2; nf++) {
            const int n0 = bn0 + wn + nf * 8 + qk * 2;
            float bv[4][2];
            #pragma unroll
            for (int op = 0; op < 4; op++) {
                bv[op][0] = bias[op * HID + n0];
                bv[op][1] = bias[op * HID + n0 + 1];
            }
            #pragma unroll
            for (int half = 0; half < 2; half++) {
                const int m = bm0 + wm + mf * 16 + qr + half * 8;
                float r0 = 0.f, r1 = 0.f;
                #pragma unroll
                for (int op = 0; op < 4; op++) {
                    const float p0 = acc[op][mf][nf][half * 2 + 0] + bv[op][0];
                    const float p1 = acc[op][mf][nf][half * 2 + 1] + bv[op][1];
                    float a0, a1;
                    switch (op) {
                        case 0:  a0 = tanhf(p0);                      a1 = tanhf(p1);                      break;
                        case 1:  a0 = fmaxf(p0, 0.f);                 a1 = fmaxf(p1, 0.f);                 break;
                        case 2:  a0 = p0 > 0.f ? p0 : expm1f(p0);     a1 = p1 > 0.f ? p1 : expm1f(p1);     break;
                        default: a0 = p0 > 0.f ? p0 : 0.01f * p0;     a1 = p1 > 0.f ? p1 : 0.01f * p1;     break;
                    }
                    const float zv = (op == 0) ? z0 : (op == 1) ? z1 : (op == 2) ? z2 : z3;
                    r0 += zv * a0; r1 += zv * a1;
                }
                float* dst = accOut + (size_t)m * HID + n0;
                if (stage != 0) {
                    float2 old = *reinterpret_cast<const float2*>(dst);
                    r0 += old.x; r1 += old.y;
                }
                float2 res; res.x = r0; res.y = r1;
                *reinterpret_cast<float2*>(dst) = res;
                if (emit_split) {
                    __half2 h2(__float2half_rn(r0), __float2half_rn(r1));
                    *reinterpret_cast<__half2*>(afOut + a_frag_idx16(m, n0, HID)) = h2;
                }
            }
        }
}

// ---------------------------------------------------------------------------
// out = tanh(acc5 @ Wout + bout)
// ---------------------------------------------------------------------------
__global__ void out_kernel(const float* __restrict__ Wout,
                           const float* __restrict__ bout,
                           float* __restrict__ out)
{
    const int gw   = (blockIdx.x * blockDim.x + threadIdx.x) >> 5;
    const int lane = threadIdx.x & 31;
    if (gw >= BATCH) return;
    const float* a = g_acc + (size_t)4 * BATCH * HID + (size_t)gw * HID;

    float s[NOUT];
    #pragma unroll
    for (int n = 0; n < NOUT; n++) s[n] = 0.f;
    for (int kk = lane; kk < HID; kk += 32) {
        const float av = a[kk];
        const float* wr = Wout + (size_t)kk * NOUT;
        #pragma unroll
        for (int n = 0; n < NOUT; n++) s[n] = fmaf(av, wr[n], s[n]);
    }
    #pragma unroll
    for (int off = 16; off; off >>= 1)
        #pragma unroll
        for (int n = 0; n < NOUT; n++)
            s[n] += __shfl_down_sync(0xffffffffu, s[n], off);
    if (lane == 0) {
        #pragma unroll
        for (int n = 0; n < NOUT; n++)
            out[(size_t)gw * NOUT + n] = tanhf(s[n] + bout[n]);
    }
}

// ---------------------------------------------------------------------------
extern "C" void kernel_launch(void* const* d_in, const int* in_sizes, int n_in,
                              void* d_out, int out_size)
{
    const float* x    = (const float*)d_in[0];
    const float* W0   = (const float*)d_in[1];
    const float* b0   = (const float*)d_in[2];
    const float* Wh   = (const float*)d_in[3];
    const float* bh   = (const float*)d_in[4];
    const float* Wout = (const float*)d_in[5];
    const float* bout = (const float*)d_in[6];
    const float* la   = (const float*)d_in[7];
    const float* eps  = (const float*)d_in[8];
    float* out = (float*)d_out;

    cudaFuncSetAttribute(stage_mma_kernel<KP0>,
                         cudaFuncAttributeMaxDynamicSharedMemorySize, SMEM_BYTES);
    cudaFuncSetAttribute(stage_mma_kernel<HID>,
                         cudaFuncAttributeMaxDynamicSharedMemorySize, SMEM_BYTES);

    z_kernel<<<1, 32>>>(la, eps);
    split_x_kernel<<<(BATCH * KP0) / 256, 256>>>(x);
    split_t0_kernel<<<20 * 32 * 12, 256>>>(W0);
    split_th_kernel<<<40 * 32 * 32, 256>>>(Wh);
    for (int k = 0; k < 5; k++) {
        dim3 grid(BATCH / BM, HID / BN, 5 - k);
        if (k == 0)
            stage_mma_kernel<KP0><<<grid, NTHREADS, SMEM_BYTES>>>(k, b0, bh);
        else
            stage_mma_kernel<HID><<<grid, NTHREADS, SMEM_BYTES>>>(k, b0, bh);
    }
    out_kernel<<<(BATCH * 32) / 256, 256>>>(Wout, bout, out);
}